// round 12
// baseline (speedup 1.0000x reference)
#include <cuda_runtime.h>
#include <cuda_fp16.h>
#include <cstdint>

#define D      1024
#define NTOK   2048
#define NB     4
#define MTOT   8192
#define NSPLIT 8

#define BK 64                        // k-chunk in elements (128 B of fp16)
#define NCH (D / BK)                 // 16
#define BLK_BYTES 16384              // one 128x64 fp16 swizzled block
#define STAGE_BYTES (3 * BLK_BYTES)  // A + B-lo + B-hi
#define NSTAGE 3
#define DSM (NSTAGE * STAGE_BYTES + 1024)
#define SWZ(x) ((x) ^ (((x) >> 3) & 0x70))

// Block layout for a [R x 1024] fp16 matrix (R multiple of 128):
//   byte(row, col) = ((row>>7)*16 + (col>>6))*16384 + SWZ((row&127)*128 + (col&63)*2)

// ---- scratch (device globals: allocation-free rule) ----
__device__ __half g_xb[MTOT * D];
__device__ __half g_wq[D * D];
__device__ __half g_wk[D * D];
__device__ __half g_q[MTOT * D];
__device__ __half g_k[MTOT * D];
__device__ float  g_s[MTOT];
__device__ float  g_u[D];
__device__ float  g_c;
__device__ float2 g_part[MTOT * NSPLIT];

// ============================ PTX helpers ============================
__device__ __forceinline__ uint32_t smem_u32(const void* p) {
    uint32_t a;
    asm("{ .reg .u64 t; cvta.to.shared.u64 t, %1; cvt.u32.u64 %0, t; }"
        : "=r"(a) : "l"(p));
    return a;
}
__device__ __forceinline__ uint32_t h2_bits(__half2 h) {
    union { __half2 h; uint32_t u; } cv;
    cv.h = h;
    return cv.u;
}
__device__ __forceinline__ void mbar_init(uint32_t bar, uint32_t cnt) {
    asm volatile("mbarrier.init.shared.b64 [%0], %1;" :: "r"(bar), "r"(cnt) : "memory");
}
__device__ __forceinline__ void mbar_arrive(uint32_t bar) {
    asm volatile("mbarrier.arrive.shared.b64 _, [%0];" :: "r"(bar) : "memory");
}
__device__ __forceinline__ void expect_tx(uint32_t bar, uint32_t bytes) {
    asm volatile("mbarrier.arrive.expect_tx.shared.b64 _, [%0], %1;"
                 :: "r"(bar), "r"(bytes) : "memory");
}
__device__ __forceinline__ void bulk_g2s(uint32_t dst, const void* src,
                                         uint32_t bytes, uint32_t bar) {
    asm volatile(
        "cp.async.bulk.shared::cluster.global.mbarrier::complete_tx::bytes "
        "[%0], [%1], %2, [%3];"
        :: "r"(dst), "l"(src), "r"(bytes), "r"(bar) : "memory");
}
__device__ __forceinline__ void bar_wait(uint32_t bar, uint32_t parity) {
    asm volatile(
        "{\n\t.reg .pred P;\n"
        "W%=:\n\t"
        "mbarrier.try_wait.parity.shared.b64 P, [%0], %1;\n\t"
        "@!P bra W%=;\n\t}"
        :: "r"(bar), "r"(parity) : "memory");
}
#define FENCE_ASYNC() asm volatile("fence.proxy.async.shared::cta;" ::: "memory")

__device__ __forceinline__ void ldsm4(uint32_t* d, uint32_t addr) {
    asm volatile("ldmatrix.sync.aligned.m8n8.x4.shared.b16 {%0,%1,%2,%3}, [%4];"
                 : "=r"(d[0]), "=r"(d[1]), "=r"(d[2]), "=r"(d[3]) : "r"(addr));
}
__device__ __forceinline__ void mma16816(float* c, const uint32_t* a,
                                         uint32_t b0, uint32_t b1) {
    asm volatile(
        "mma.sync.aligned.m16n8k16.row.col.f32.f16.f16.f32 "
        "{%0,%1,%2,%3}, {%4,%5,%6,%7}, {%8,%9}, {%0,%1,%2,%3};"
        : "+f"(c[0]), "+f"(c[1]), "+f"(c[2]), "+f"(c[3])
        : "r"(a[0]), "r"(a[1]), "r"(a[2]), "r"(a[3]), "r"(b0), "r"(b1));
}

// fast 2^t on the FMA pipe
__device__ __forceinline__ float fexp2(float t) {
    t = fmaxf(t, -60.0f);
    float z = t + 12582912.0f;            // 1.5*2^23 rounding trick
    int   ki = __float_as_int(z);
    float n  = z - 12582912.0f;
    float f  = t - n;
    float p = 0.0013333558f;
    p = fmaf(p, f, 0.0096181291f);
    p = fmaf(p, f, 0.0555041087f);
    p = fmaf(p, f, 0.2402265070f);
    p = fmaf(p, f, 0.6931471806f);
    p = fmaf(p, f, 1.0f);
    return __int_as_float(__float_as_int(p) + (ki << 23));
}

// barrier layout: full[s] at mbar + s*8, empty[s] at mbar + 24 + s*8
#define FULL(s)  (mbar + (uint32_t)(s) * 8)
#define EMPTY(s) (mbar + 24 + (uint32_t)(s) * 8)

// ============================ GEMM microkernel ============================
// C[128x256] += A_tile[128xD] * B_tile[256xD]^T, pre-swizzled block layout.
// Warp tile 64x64 (8 warps = 2M x 4N). 3-stage bulk-copy pipeline with
// producer/consumer mbarriers. srcB spans two row-tiles (lo, hi).
__device__ __forceinline__ void gemm_tile(uint32_t sbase, uint32_t mbar,
                                          const char* srcA,
                                          const char* srcBlo,
                                          const char* srcBhi,
                                          int tid, float c[4][8][4]) {
    const int lane = tid & 31, warp = tid >> 5;
    const int mw = warp & 1, nw = warp >> 1;       // nw 0..3 -> 64-col group
    const int q2 = lane >> 3, r = lane & 7;
    const int kbh = (q2 >> 1) * 16;
    const uint32_t bbase = BLK_BYTES + (uint32_t)(nw >> 1) * BLK_BYTES; // lo/hi
    uint32_t aoff[4], boff[4];
    #pragma unroll
    for (int mt = 0; mt < 4; mt++)
        aoff[mt] = (uint32_t)((mw * 64 + mt * 16 + (q2 & 1) * 8 + r) * 128 + kbh);
    #pragma unroll
    for (int nb = 0; nb < 4; nb++)
        boff[nb] = (uint32_t)(((nw & 1) * 64 + nb * 16 + (q2 & 1) * 8 + r) * 128 + kbh);

    int cf[NSTAGE] = {0, 0, 0};
    int ic[NSTAGE] = {0, 0, 0};

    // prologue: fill all stages
    #pragma unroll
    for (int s = 0; s < NSTAGE; s++) {
        if (tid == 0) {
            expect_tx(FULL(s), 3 * BLK_BYTES);
            uint32_t sA = sbase + s * STAGE_BYTES;
            bulk_g2s(sA,                 srcA   + s * BLK_BYTES, BLK_BYTES, FULL(s));
            bulk_g2s(sA + BLK_BYTES,     srcBlo + s * BLK_BYTES, BLK_BYTES, FULL(s));
            bulk_g2s(sA + 2 * BLK_BYTES, srcBhi + s * BLK_BYTES, BLK_BYTES, FULL(s));
        }
        ic[s] = 1;
    }

    #pragma unroll 1
    for (int g = 0; g < NCH; g++) {
        int s = g % NSTAGE;
        bar_wait(FULL(s), cf[s] & 1);
        cf[s]++;

        uint32_t sA = sbase + s * STAGE_BYTES;
        uint32_t sB = sA + bbase;
        #pragma unroll
        for (int ks = 0; ks < 4; ks++) {
            int kd = ks * 32;
            uint32_t a[4][4], b[4][4];
            #pragma unroll
            for (int mt = 0; mt < 4; mt++) ldsm4(a[mt], sA + SWZ(aoff[mt] + kd));
            #pragma unroll
            for (int nb = 0; nb < 4; nb++) ldsm4(b[nb], sB + SWZ(boff[nb] + kd));
            #pragma unroll
            for (int mt = 0; mt < 4; mt++)
                #pragma unroll
                for (int nt = 0; nt < 8; nt++)
                    mma16816(c[mt][nt], a[mt],
                             b[nt >> 1][nt & 1], b[nt >> 1][(nt & 1) + 2]);
        }
        if (lane == 0) mbar_arrive(EMPTY(s));

        if (g + NSTAGE < NCH) {
            if (tid == 0) {
                bar_wait(EMPTY(s), (ic[s] - 1) & 1);
                expect_tx(FULL(s), 3 * BLK_BYTES);
                bulk_g2s(sA,                 srcA   + (size_t)(g + NSTAGE) * BLK_BYTES,
                         BLK_BYTES, FULL(s));
                bulk_g2s(sA + BLK_BYTES,     srcBlo + (size_t)(g + NSTAGE) * BLK_BYTES,
                         BLK_BYTES, FULL(s));
                bulk_g2s(sA + 2 * BLK_BYTES, srcBhi + (size_t)(g + NSTAGE) * BLK_BYTES,
                         BLK_BYTES, FULL(s));
            }
            ic[s]++;
        }
    }
}

__device__ __forceinline__ void mbar_setup(uint32_t mbar, int tid) {
    if (tid == 0) {
        #pragma unroll
        for (int s = 0; s < NSTAGE; s++) {
            mbar_init(FULL(s), 1);
            mbar_init(EMPTY(s), 8);     // one arrival per warp
        }
        FENCE_ASYNC();
    }
    __syncthreads();
}

// ============================ small kernels ============================
__global__ void conv_kernel(const float* __restrict__ x,
                            const float* __restrict__ Wq,
                            const float* __restrict__ Wk) {
    size_t gid = (size_t)blockIdx.x * 256 + threadIdx.x;
    size_t e = gid * 8;
    const float* src; char* dst; size_t off;
    if (e < (size_t)MTOT * D)        { src = x;  dst = (char*)g_xb; off = e; }
    else if (e < (size_t)MTOT*D + (size_t)D*D)
                                     { src = Wq; dst = (char*)g_wq; off = e - (size_t)MTOT*D; }
    else                             { src = Wk; dst = (char*)g_wk; off = e - (size_t)MTOT*D - (size_t)D*D; }
    int row = (int)(off >> 10);
    int col = (int)(off & 1023);
    const float4* s4 = (const float4*)(src + off);
    float4 v0 = s4[0], v1 = s4[1];
    uint4 o;
    o.x = h2_bits(__floats2half2_rn(v0.x, v0.y));
    o.y = h2_bits(__floats2half2_rn(v0.z, v0.w));
    o.z = h2_bits(__floats2half2_rn(v1.x, v1.y));
    o.w = h2_bits(__floats2half2_rn(v1.z, v1.w));
    uint32_t inblk = SWZ((uint32_t)((row & 127) * 128 + (col & 63) * 2));
    size_t byte = ((size_t)((row >> 7) * 16 + (col >> 6))) * BLK_BYTES + inblk;
    *(uint4*)(dst + byte) = o;
}

__global__ void prep_u_kernel(const float* __restrict__ Wv,
                              const float* __restrict__ bv,
                              const float* __restrict__ Ww) {
    if (blockIdx.x < 4) {
        int e = blockIdx.x * 256 + threadIdx.x;
        float sum = 0.f;
        #pragma unroll 8
        for (int d = 0; d < D; d++) sum = fmaf(Ww[d], Wv[d * D + e], sum);
        g_u[e] = sum;
    } else {
        __shared__ float red[256];
        float s = 0.f;
        for (int d = threadIdx.x; d < D; d += 256) s = fmaf(Ww[d], bv[d], s);
        red[threadIdx.x] = s;
        __syncthreads();
        for (int off = 128; off > 0; off >>= 1) {
            if (threadIdx.x < off) red[threadIdx.x] += red[threadIdx.x + off];
            __syncthreads();
        }
        if (threadIdx.x == 0) g_c = red[0];
    }
}

__global__ void s_kernel(const float* __restrict__ x) {
    int row  = blockIdx.x * 8 + (threadIdx.x >> 5);
    int lane = threadIdx.x & 31;
    const float4* xr = (const float4*)(x + (size_t)row * D);
    const float4* u4 = (const float4*)g_u;
    float sum = 0.f;
    #pragma unroll
    for (int i = 0; i < 8; i++) {
        float4 a = xr[lane + i * 32];
        float4 b = u4[lane + i * 32];
        sum += a.x * b.x + a.y * b.y + a.z * b.z + a.w * b.w;
    }
    #pragma unroll
    for (int off = 16; off > 0; off >>= 1)
        sum += __shfl_xor_sync(0xffffffffu, sum, off);
    if (lane == 0) g_s[row] = sum + g_c;
}

// ============================ projection GEMM ============================
// CTA tile 128 x 256, grid (MTOT/128, D/256, 2)
__global__ __launch_bounds__(256, 1)
void proj_kernel(const float* __restrict__ bq, const float* __restrict__ bk) {
    extern __shared__ char dsm[];
    __shared__ __align__(8) uint64_t s_bar[2 * NSTAGE];
    __shared__ float s_bias[256];

    const char* Wb    = blockIdx.z ? (const char*)g_wk : (const char*)g_wq;
    const float* bias = blockIdx.z ? bk : bq;
    char* out         = blockIdx.z ? (char*)g_k : (char*)g_q;
    const int rt   = blockIdx.x;          // row tile (128 rows)
    const int ct   = blockIdx.y;          // col tile (256 cols)
    const int tid  = threadIdx.x;
    uint32_t sbase = (smem_u32(dsm) + 1023u) & ~1023u;
    uint32_t mbar  = smem_u32(s_bar);

    s_bias[tid] = bias[ct * 256 + tid];
    mbar_setup(mbar, tid);

    float cacc[4][8][4];
    #pragma unroll
    for (int a = 0; a < 4; a++)
        #pragma unroll
        for (int b = 0; b < 8; b++)
            #pragma unroll
            for (int e = 0; e < 4; e++) cacc[a][b][e] = 0.f;

    // B row-tiles: output cols ct*256 .. ct*256+255 = W rows; in block layout
    // these are row-tiles 2*ct (lo) and 2*ct+1 (hi).
    gemm_tile(sbase, mbar,
              (const char*)g_xb + (size_t)rt * 16 * BLK_BYTES,
              Wb + (size_t)(2 * ct)     * 16 * BLK_BYTES,
              Wb + (size_t)(2 * ct + 1) * 16 * BLK_BYTES,
              tid, cacc);

    const int lane = tid & 31, warp = tid >> 5;
    const int mw = warp & 1, nw = warp >> 1;
    const int gq = lane >> 2, tg = lane & 3;
    #pragma unroll
    for (int mt = 0; mt < 4; mt++) {
        int rowL = mw * 64 + mt * 16 + gq;
        #pragma unroll
        for (int nt = 0; nt < 8; nt++) {
            int colL = nw * 64 + nt * 8 + 2 * tg;       // 0..255 within tile
            int col  = ct * 256 + colL;
            float b0 = s_bias[colL], b1 = s_bias[colL + 1];
            float* cc = cacc[mt][nt];
            size_t blk = ((size_t)(rt * 16 + (col >> 6))) * BLK_BYTES;
            uint32_t cb = (uint32_t)((col & 63) * 2);
            *(__half2*)(out + blk + SWZ((uint32_t)( rowL      * 128) + cb)) =
                __floats2half2_rn(cc[0] + b0, cc[1] + b1);
            *(__half2*)(out + blk + SWZ((uint32_t)((rowL + 8) * 128) + cb)) =
                __floats2half2_rn(cc[2] + b0, cc[3] + b1);
        }
    }
}

// ============================ attention kernel ============================
// CTA: 128 q-rows x 256 keys, grid (NTOK/128, NTOK/256, NB)
__global__ __launch_bounds__(256, 1)
void attn_kernel() {
    extern __shared__ char dsm[];
    __shared__ __align__(8) uint64_t s_bar[2 * NSTAGE];
    __shared__ float s_sm[256];
    __shared__ float s_red[128][4][2];

    const int b     = blockIdx.z;
    const int split = blockIdx.y;          // 256-key block index (0..7)
    const int nt_q  = blockIdx.x;
    const int row0  = b * NTOK + nt_q * 128;
    const int kb    = b * NTOK + split * 256;
    const int tid   = threadIdx.x;
    const float CLOG = 0.045084220027780106f;   // log2(e)/sqrt(D)
    uint32_t sbase = (smem_u32(dsm) + 1023u) & ~1023u;
    uint32_t mbar  = smem_u32(s_bar);

    const int lane = tid & 31, warp = tid >> 5;
    const int mw = warp & 1, nw = warp >> 1;
    const int gq = lane >> 2, tg = lane & 3;

    s_sm[tid] = g_s[kb + tid];
    mbar_setup(mbar, tid);                 // includes __syncthreads

    float cacc[4][8][4];
    #pragma unroll
    for (int a = 0; a < 4; a++)
        #pragma unroll
        for (int c = 0; c < 8; c++)
            #pragma unroll
            for (int e = 0; e < 4; e++) cacc[a][c][e] = 0.f;

    gemm_tile(sbase, mbar,
              (const char*)g_q + (size_t)(row0 >> 7) * 16 * BLK_BYTES,
              (const char*)g_k + (size_t)(kb   >> 7) * 16 * BLK_BYTES,
              (const char*)g_k + (size_t)((kb >> 7) + 1) * 16 * BLK_BYTES,
              tid, cacc);

    float num[4][2], den[4][2];
    #pragma unroll
    for (int mt = 0; mt < 4; mt++)
        #pragma unroll
        for (int h = 0; h < 2; h++) { num[mt][h] = 0.f; den[mt][h] = 0.f; }

    #pragma unroll
    for (int mt = 0; mt < 4; mt++)
        #pragma unroll
        for (int nt = 0; nt < 8; nt++) {
            int colL = nw * 64 + nt * 8 + 2 * tg;
            float s0 = s_sm[colL], s1 = s_sm[colL + 1];
            float* cc = cacc[mt][nt];
            float e0 = fexp2(fmaf(cc[0], CLOG, -4.0f));
            float e1 = fexp2(fmaf(cc[1], CLOG, -4.0f));
            float e2 = fexp2(fmaf(cc[2], CLOG, -4.0f));
            float e3 = fexp2(fmaf(cc[3], CLOG, -4.0f));
            den[mt][0] += e0 + e1;
            den[mt][1] += e2 + e3;
            num[mt][0] = fmaf(e0, s0, fmaf(e1, s1, num[mt][0]));
            num[mt][1] = fmaf(e2, s0, fmaf(e3, s1, num[mt][1]));
        }

    // reduce over the 4 tg lanes sharing a row
    #pragma unroll
    for (int mt = 0; mt < 4; mt++)
        #pragma unroll
        for (int h = 0; h < 2; h++) {
            num[mt][h] += __shfl_xor_sync(0xffffffffu, num[mt][h], 1);
            num[mt][h] += __shfl_xor_sync(0xffffffffu, num[mt][h], 2);
            den[mt][h] += __shfl_xor_sync(0xffffffffu, den[mt][h], 1);
            den[mt][h] += __shfl_xor_sync(0xffffffffu, den[mt][h], 2);
        }
    if (tg == 0) {
        #pragma unroll
        for (int mt = 0; mt < 4; mt++)
            #pragma unroll
            for (int h = 0; h < 2; h++) {
                int rowl = mw * 64 + mt * 16 + h * 8 + gq;
                s_red[rowl][nw][0] = num[mt][h];
                s_red[rowl][nw][1] = den[mt][h];
            }
    }
    __syncthreads();
    if (tid < 128) {
        float n = 0.f, d = 0.f;
        #pragma unroll
        for (int w = 0; w < 4; w++) { n += s_red[tid][w][0]; d += s_red[tid][w][1]; }
        g_part[(size_t)(row0 + tid) * NSPLIT + split] = make_float2(n, d);
    }
}

// ============================ combine ============================
__global__ void combine_kernel(const float* __restrict__ bw,
                               float* __restrict__ out) {
    int row = blockIdx.x * 256 + threadIdx.x;
    float n = 0.f, d = 0.f;
    #pragma unroll
    for (int s = 0; s < NSPLIT; s++) {
        float2 p = g_part[(size_t)row * NSPLIT + s];
        n += p.x; d += p.y;
    }
    out[row] = n / d + bw[0];
}

// ============================ launcher ============================
extern "C" void kernel_launch(void* const* d_in, const int* in_sizes, int n_in,
                              void* d_out, int out_size) {
    const float* x  = (const float*)d_in[0];
    const float* Wq = (const float*)d_in[1];
    const float* bq = (const float*)d_in[2];
    const float* Wk = (const float*)d_in[3];
    const float* bk = (const float*)d_in[4];
    const float* Wv = (const float*)d_in[5];
    const float* bv = (const float*)d_in[6];
    const float* Ww = (const float*)d_in[7];
    const float* bw = (const float*)d_in[8];
    float* out = (float*)d_out;

    cudaFuncSetAttribute(proj_kernel,
        cudaFuncAttributeMaxDynamicSharedMemorySize, DSM);
    cudaFuncSetAttribute(attn_kernel,
        cudaFuncAttributeMaxDynamicSharedMemorySize, DSM);

    conv_kernel<<<5120, 256>>>(x, Wq, Wk);
    prep_u_kernel<<<5, 256>>>(Wv, bv, Ww);
    s_kernel<<<MTOT / 8, 256>>>(x);

    dim3 g3(MTOT / 128, D / 256, 2);
    proj_kernel<<<g3, 256, DSM>>>(bq, bk);

    dim3 g4(NTOK / 128, NTOK / 256, NB);
    attn_kernel<<<g4, 256, DSM>>>();

    combine_kernel<<<MTOT / 256, 256>>>(bw, out);
}

// round 13
// speedup vs baseline: 1.0652x; 1.0652x over previous
#include <cuda_runtime.h>
#include <cuda_fp16.h>
#include <cstdint>

#define D      1024
#define NTOK   2048
#define NB     4
#define MTOT   8192
#define NSPLIT 8

#define BK 64                       // k-chunk in elements (128 B of fp16)
#define NCH (D / BK)                // 16
#define BLK_BYTES 16384             // one 128x64 fp16 swizzled block
#define A_BYTES   BLK_BYTES
#define STAGE_BYTES (2 * BLK_BYTES) // A + B block
#define NSTAGE 3
#define DSM (NSTAGE * STAGE_BYTES + 1024)   // + align slack
#define SWZ(x) ((x) ^ (((x) >> 3) & 0x70))

#define NPROJ_TILES 1024            // 64 rt x 8 ct x 2 z
#define NATTN_TILES 512             // 4 b x 8 split x 16 ntq
#define PERSIST_CTAS 296            // 2 per SM x 148

// Block layout for a [R x 1024] fp16 matrix (R multiple of 128):
//   byte(row, col) = ((row>>7)*16 + (col>>6))*16384 + SWZ((row&127)*128 + (col&63)*2)

// ---- scratch (device globals: allocation-free rule) ----
__device__ __half g_xb[MTOT * D];
__device__ __half g_wq[D * D];
__device__ __half g_wk[D * D];
__device__ __half g_q[MTOT * D];
__device__ __half g_k[MTOT * D];
__device__ float  g_s[MTOT];
__device__ float  g_u[D];
__device__ float  g_c;
__device__ float2 g_part[MTOT * NSPLIT];
__device__ unsigned int g_ctr[2];   // work-stealing tickets (proj, attn)

// ============================ PTX helpers ============================
__device__ __forceinline__ uint32_t smem_u32(const void* p) {
    uint32_t a;
    asm("{ .reg .u64 t; cvta.to.shared.u64 t, %1; cvt.u32.u64 %0, t; }"
        : "=r"(a) : "l"(p));
    return a;
}
__device__ __forceinline__ uint32_t h2_bits(__half2 h) {
    union { __half2 h; uint32_t u; } cv;
    cv.h = h;
    return cv.u;
}
__device__ __forceinline__ void mbar_init(uint32_t bar, uint32_t cnt) {
    asm volatile("mbarrier.init.shared.b64 [%0], %1;" :: "r"(bar), "r"(cnt) : "memory");
}
__device__ __forceinline__ void expect_tx(uint32_t bar, uint32_t bytes) {
    asm volatile("mbarrier.arrive.expect_tx.shared.b64 _, [%0], %1;"
                 :: "r"(bar), "r"(bytes) : "memory");
}
__device__ __forceinline__ void bulk_g2s(uint32_t dst, const void* src,
                                         uint32_t bytes, uint32_t bar) {
    asm volatile(
        "cp.async.bulk.shared::cluster.global.mbarrier::complete_tx::bytes "
        "[%0], [%1], %2, [%3];"
        :: "r"(dst), "l"(src), "r"(bytes), "r"(bar) : "memory");
}
__device__ __forceinline__ void bar_wait(uint32_t bar, uint32_t parity) {
    asm volatile(
        "{\n\t.reg .pred P;\n"
        "W%=:\n\t"
        "mbarrier.try_wait.parity.shared.b64 P, [%0], %1;\n\t"
        "@!P bra W%=;\n\t}"
        :: "r"(bar), "r"(parity) : "memory");
}
#define FENCE_ASYNC() asm volatile("fence.proxy.async.shared::cta;" ::: "memory")

__device__ __forceinline__ void ldsm4(uint32_t* d, uint32_t addr) {
    asm volatile("ldmatrix.sync.aligned.m8n8.x4.shared.b16 {%0,%1,%2,%3}, [%4];"
                 : "=r"(d[0]), "=r"(d[1]), "=r"(d[2]), "=r"(d[3]) : "r"(addr));
}
__device__ __forceinline__ void mma16816(float* c, const uint32_t* a,
                                         uint32_t b0, uint32_t b1) {
    asm volatile(
        "mma.sync.aligned.m16n8k16.row.col.f32.f16.f16.f32 "
        "{%0,%1,%2,%3}, {%4,%5,%6,%7}, {%8,%9}, {%0,%1,%2,%3};"
        : "+f"(c[0]), "+f"(c[1]), "+f"(c[2]), "+f"(c[3])
        : "r"(a[0]), "r"(a[1]), "r"(a[2]), "r"(a[3]), "r"(b0), "r"(b1));
}

// fast 2^t on the FMA pipe
__device__ __forceinline__ float fexp2(float t) {
    t = fmaxf(t, -60.0f);
    float z = t + 12582912.0f;            // 1.5*2^23 rounding trick
    int   ki = __float_as_int(z);
    float n  = z - 12582912.0f;
    float f  = t - n;
    float p = 0.0013333558f;
    p = fmaf(p, f, 0.0096181291f);
    p = fmaf(p, f, 0.0555041087f);
    p = fmaf(p, f, 0.2402265070f);
    p = fmaf(p, f, 0.6931471806f);
    p = fmaf(p, f, 1.0f);
    return __int_as_float(__float_as_int(p) + (ki << 23));
}

// ============================ GEMM microkernel ============================
// C[128x128] += A_tile * B_tile^T over K=1024, operands in pre-swizzled block
// layout. 3-stage bulk-copy pipeline; cnt[] carries mbar phases across calls.
__device__ __forceinline__ void gemm_tile(uint32_t sbase, uint32_t mbar,
                                          const char* srcA, const char* srcB,
                                          int tid, int cnt[NSTAGE],
                                          float c[4][4][4]) {
    const int lane = tid & 31, warp = tid >> 5;
    const int mw = warp & 1, nw = warp >> 1;
    const int q2 = lane >> 3, r = lane & 7;
    const int kbh = (q2 >> 1) * 16;
    uint32_t aoff[4], boff[2];
    #pragma unroll
    for (int mt = 0; mt < 4; mt++)
        aoff[mt] = (uint32_t)((mw * 64 + mt * 16 + (q2 & 1) * 8 + r) * 128 + kbh);
    #pragma unroll
    for (int nb = 0; nb < 2; nb++)
        boff[nb] = (uint32_t)((nw * 32 + nb * 16 + (q2 & 1) * 8 + r) * 128 + kbh);

    if (tid == 0) {
        #pragma unroll
        for (int s = 0; s < NSTAGE; s++) {
            expect_tx(mbar + s * 8, 2 * BLK_BYTES);
            bulk_g2s(sbase + s * STAGE_BYTES,           srcA + s * BLK_BYTES,
                     BLK_BYTES, mbar + s * 8);
            bulk_g2s(sbase + s * STAGE_BYTES + A_BYTES, srcB + s * BLK_BYTES,
                     BLK_BYTES, mbar + s * 8);
        }
    }

    #pragma unroll 1
    for (int g = 0; g < NCH; g++) {
        int s = g % NSTAGE;
        bar_wait(mbar + s * 8, cnt[s] & 1);
        cnt[s]++;

        uint32_t sA = sbase + s * STAGE_BYTES;
        uint32_t sB = sA + A_BYTES;
        #pragma unroll
        for (int ks = 0; ks < 4; ks++) {
            int kd = ks * 32;
            uint32_t a[4][4], b[2][4];
            #pragma unroll
            for (int mt = 0; mt < 4; mt++) ldsm4(a[mt], sA + SWZ(aoff[mt] + kd));
            #pragma unroll
            for (int nb = 0; nb < 2; nb++) ldsm4(b[nb], sB + SWZ(boff[nb] + kd));
            #pragma unroll
            for (int mt = 0; mt < 4; mt++)
                #pragma unroll
                for (int nt = 0; nt < 4; nt++)
                    mma16816(c[mt][nt], a[mt],
                             b[nt >> 1][nt & 1], b[nt >> 1][(nt & 1) + 2]);
        }
        __syncthreads();                  // all threads done reading stage s
        if (tid == 0 && g + NSTAGE < NCH) {
            expect_tx(mbar + s * 8, 2 * BLK_BYTES);
            bulk_g2s(sA,           srcA + (size_t)(g + NSTAGE) * BLK_BYTES,
                     BLK_BYTES, mbar + s * 8);
            bulk_g2s(sA + A_BYTES, srcB + (size_t)(g + NSTAGE) * BLK_BYTES,
                     BLK_BYTES, mbar + s * 8);
        }
    }
}

__device__ __forceinline__ void mbar_setup(uint32_t mbar, int tid) {
    if (tid == 0) {
        #pragma unroll
        for (int s = 0; s < NSTAGE; s++) mbar_init(mbar + s * 8, 1);
        FENCE_ASYNC();
    }
    __syncthreads();
}

// ============================ small kernels ============================
// fp32 -> fp16 swizzled-block conversion for x, Wq, Wk (8 elems/thread)
__global__ void conv_kernel(const float* __restrict__ x,
                            const float* __restrict__ Wq,
                            const float* __restrict__ Wk) {
    size_t gid = (size_t)blockIdx.x * 256 + threadIdx.x;
    size_t e = gid * 8;
    const float* src; char* dst; size_t off;
    if (e < (size_t)MTOT * D)        { src = x;  dst = (char*)g_xb; off = e; }
    else if (e < (size_t)MTOT*D + (size_t)D*D)
                                     { src = Wq; dst = (char*)g_wq; off = e - (size_t)MTOT*D; }
    else                             { src = Wk; dst = (char*)g_wk; off = e - (size_t)MTOT*D - (size_t)D*D; }
    int row = (int)(off >> 10);
    int col = (int)(off & 1023);
    const float4* s4 = (const float4*)(src + off);
    float4 v0 = s4[0], v1 = s4[1];
    uint4 o;
    o.x = h2_bits(__floats2half2_rn(v0.x, v0.y));
    o.y = h2_bits(__floats2half2_rn(v0.z, v0.w));
    o.z = h2_bits(__floats2half2_rn(v1.x, v1.y));
    o.w = h2_bits(__floats2half2_rn(v1.z, v1.w));
    uint32_t inblk = SWZ((uint32_t)((row & 127) * 128 + (col & 63) * 2));
    size_t byte = ((size_t)((row >> 7) * 16 + (col >> 6))) * BLK_BYTES + inblk;
    *(uint4*)(dst + byte) = o;
}

__global__ void prep_u_kernel(const float* __restrict__ Wv,
                              const float* __restrict__ bv,
                              const float* __restrict__ Ww) {
    if (blockIdx.x < 4) {
        int e = blockIdx.x * 256 + threadIdx.x;
        float sum = 0.f;
        #pragma unroll 8
        for (int d = 0; d < D; d++) sum = fmaf(Ww[d], Wv[d * D + e], sum);
        g_u[e] = sum;
    } else {
        __shared__ float red[256];
        float s = 0.f;
        for (int d = threadIdx.x; d < D; d += 256) s = fmaf(Ww[d], bv[d], s);
        red[threadIdx.x] = s;
        __syncthreads();
        for (int off = 128; off > 0; off >>= 1) {
            if (threadIdx.x < off) red[threadIdx.x] += red[threadIdx.x + off];
            __syncthreads();
        }
        if (threadIdx.x == 0) {
            g_c = red[0];
            g_ctr[0] = 0;            // reset work-stealing tickets
            g_ctr[1] = 0;
        }
    }
}

__global__ void s_kernel(const float* __restrict__ x) {
    int row  = blockIdx.x * 8 + (threadIdx.x >> 5);
    int lane = threadIdx.x & 31;
    const float4* xr = (const float4*)(x + (size_t)row * D);
    const float4* u4 = (const float4*)g_u;
    float sum = 0.f;
    #pragma unroll
    for (int i = 0; i < 8; i++) {
        float4 a = xr[lane + i * 32];
        float4 b = u4[lane + i * 32];
        sum += a.x * b.x + a.y * b.y + a.z * b.z + a.w * b.w;
    }
    #pragma unroll
    for (int off = 16; off > 0; off >>= 1)
        sum += __shfl_xor_sync(0xffffffffu, sum, off);
    if (lane == 0) g_s[row] = sum + g_c;
}

// ============================ projection GEMM ============================
// Persistent: 296 CTAs work-steal 1024 tiles (64 rt x 8 ct x 2 z).
__global__ __launch_bounds__(256, 2)
void proj_kernel(const float* __restrict__ bq, const float* __restrict__ bk) {
    extern __shared__ char dsm[];
    __shared__ __align__(8) uint64_t s_bar[NSTAGE];
    __shared__ float s_bias[128];
    __shared__ int s_tile;

    const int tid  = threadIdx.x;
    uint32_t sbase = (smem_u32(dsm) + 1023u) & ~1023u;
    uint32_t mbar  = smem_u32(s_bar);
    mbar_setup(mbar, tid);

    const int lane = tid & 31, warp = tid >> 5;
    const int mw = warp & 1, nw = warp >> 1;
    const int gq = lane >> 2, tg = lane & 3;
    int cnt[NSTAGE] = {0, 0, 0};

    for (;;) {
        __syncthreads();                 // prior epilogue done with s_bias
        if (tid == 0) s_tile = (int)atomicAdd(&g_ctr[0], 1u);
        __syncthreads();
        int t = s_tile;
        if (t >= NPROJ_TILES) break;
        int z  = t >> 9;                 // consecutive tickets share z, ct
        int rm = t & 511;
        int ct = rm >> 6;
        int rt = rm & 63;

        const char* Wb    = z ? (const char*)g_wk : (const char*)g_wq;
        char* out         = z ? (char*)g_k : (char*)g_q;
        if (tid < 128) s_bias[tid] = (z ? bk : bq)[ct * 128 + tid];
        // (gemm_tile's first internal __syncthreads orders s_bias writes)

        float cacc[4][4][4];
        #pragma unroll
        for (int a = 0; a < 4; a++)
            #pragma unroll
            for (int b = 0; b < 4; b++)
                #pragma unroll
                for (int e = 0; e < 4; e++) cacc[a][b][e] = 0.f;

        gemm_tile(sbase, mbar,
                  (const char*)g_xb + (size_t)rt * 16 * BLK_BYTES,
                  Wb + (size_t)ct * 16 * BLK_BYTES,
                  tid, cnt, cacc);

        #pragma unroll
        for (int mt = 0; mt < 4; mt++) {
            int rowL = mw * 64 + mt * 16 + gq;
            #pragma unroll
            for (int nt = 0; nt < 4; nt++) {
                int colL = nw * 32 + nt * 8 + 2 * tg;   // 0..127 within tile
                int col  = ct * 128 + colL;
                float b0 = s_bias[colL], b1 = s_bias[colL + 1];
                float* cc = cacc[mt][nt];
                size_t blk = ((size_t)(rt * 16 + (col >> 6))) * BLK_BYTES;
                uint32_t cb = (uint32_t)((col & 63) * 2);
                *(__half2*)(out + blk + SWZ((uint32_t)( rowL      * 128) + cb)) =
                    __floats2half2_rn(cc[0] + b0, cc[1] + b1);
                *(__half2*)(out + blk + SWZ((uint32_t)((rowL + 8) * 128) + cb)) =
                    __floats2half2_rn(cc[2] + b0, cc[3] + b1);
            }
        }
    }
}

// ============================ attention kernel ============================
// Persistent: 296 CTAs work-steal 512 tiles (4 b x 8 split x 16 ntq).
__global__ __launch_bounds__(256, 2)
void attn_kernel() {
    extern __shared__ char dsm[];
    __shared__ __align__(8) uint64_t s_bar[NSTAGE];
    __shared__ float s_sm[128];
    __shared__ float s_red[128][4][2];
    __shared__ int s_tile;

    const int tid  = threadIdx.x;
    const float CLOG = 0.045084220027780106f;   // log2(e)/sqrt(D)
    uint32_t sbase = (smem_u32(dsm) + 1023u) & ~1023u;
    uint32_t mbar  = smem_u32(s_bar);
    mbar_setup(mbar, tid);

    const int lane = tid & 31, warp = tid >> 5;
    const int mw = warp & 1, nw = warp >> 1;
    const int gq = lane >> 2, tg = lane & 3;
    int cnt[NSTAGE] = {0, 0, 0};

    for (;;) {
        __syncthreads();                 // prior epilogue done with smem
        if (tid == 0) s_tile = (int)atomicAdd(&g_ctr[1], 1u);
        __syncthreads();
        int t = s_tile;
        if (t >= NATTN_TILES) break;
        int b     = t >> 7;              // consecutive tickets share b, split
        int rm    = t & 127;
        int split = rm >> 4;
        int nt_q  = rm & 15;
        const int row0 = b * NTOK + nt_q * 128;

        float num[4][2], den[4][2];
        #pragma unroll
        for (int mt = 0; mt < 4; mt++)
            #pragma unroll
            for (int h = 0; h < 2; h++) { num[mt][h] = 0.f; den[mt][h] = 0.f; }

        #pragma unroll 1
        for (int blk = 0; blk < 2; blk++) {
            const int kb = b * NTOK + split * 256 + blk * 128;
            if (tid < 128) s_sm[tid] = g_s[kb + tid];
            // (gemm_tile's internal __syncthreads orders this before epilogue)

            float cacc[4][4][4];
            #pragma unroll
            for (int a = 0; a < 4; a++)
                #pragma unroll
                for (int c = 0; c < 4; c++)
                    #pragma unroll
                    for (int e = 0; e < 4; e++) cacc[a][c][e] = 0.f;

            gemm_tile(sbase, mbar,
                      (const char*)g_q + (size_t)(row0 >> 7) * 16 * BLK_BYTES,
                      (const char*)g_k + (size_t)(kb   >> 7) * 16 * BLK_BYTES,
                      tid, cnt, cacc);

            #pragma unroll
            for (int mt = 0; mt < 4; mt++)
                #pragma unroll
                for (int nt = 0; nt < 4; nt++) {
                    int colL = nw * 32 + nt * 8 + 2 * tg;
                    float s0 = s_sm[colL], s1 = s_sm[colL + 1];
                    float* cc = cacc[mt][nt];
                    float e0 = fexp2(fmaf(cc[0], CLOG, -4.0f));
                    float e1 = fexp2(fmaf(cc[1], CLOG, -4.0f));
                    float e2 = fexp2(fmaf(cc[2], CLOG, -4.0f));
                    float e3 = fexp2(fmaf(cc[3], CLOG, -4.0f));
                    den[mt][0] += e0 + e1;
                    den[mt][1] += e2 + e3;
                    num[mt][0] = fmaf(e0, s0, fmaf(e1, s1, num[mt][0]));
                    num[mt][1] = fmaf(e2, s0, fmaf(e3, s1, num[mt][1]));
                }
            __syncthreads();   // protect s_sm before next block overwrites
        }

        // reduce over the 4 tg lanes sharing a row
        #pragma unroll
        for (int mt = 0; mt < 4; mt++)
            #pragma unroll
            for (int h = 0; h < 2; h++) {
                num[mt][h] += __shfl_xor_sync(0xffffffffu, num[mt][h], 1);
                num[mt][h] += __shfl_xor_sync(0xffffffffu, num[mt][h], 2);
                den[mt][h] += __shfl_xor_sync(0xffffffffu, den[mt][h], 1);
                den[mt][h] += __shfl_xor_sync(0xffffffffu, den[mt][h], 2);
            }
        if (tg == 0) {
            #pragma unroll
            for (int mt = 0; mt < 4; mt++)
                #pragma unroll
                for (int h = 0; h < 2; h++) {
                    int rowl = mw * 64 + mt * 16 + h * 8 + gq;
                    s_red[rowl][nw][0] = num[mt][h];
                    s_red[rowl][nw][1] = den[mt][h];
                }
        }
        __syncthreads();
        if (tid < 128) {
            float n = 0.f, d = 0.f;
            #pragma unroll
            for (int w = 0; w < 4; w++) { n += s_red[tid][w][0]; d += s_red[tid][w][1]; }
            g_part[(size_t)(row0 + tid) * NSPLIT + split] = make_float2(n, d);
        }
    }
}

// ============================ combine ============================
__global__ void combine_kernel(const float* __restrict__ bw,
                               float* __restrict__ out) {
    int row = blockIdx.x * 256 + threadIdx.x;
    float n = 0.f, d = 0.f;
    #pragma unroll
    for (int s = 0; s < NSPLIT; s++) {
        float2 p = g_part[(size_t)row * NSPLIT + s];
        n += p.x; d += p.y;
    }
    out[row] = n / d + bw[0];
}

// ============================ launcher ============================
extern "C" void kernel_launch(void* const* d_in, const int* in_sizes, int n_in,
                              void* d_out, int out_size) {
    const float* x  = (const float*)d_in[0];
    const float* Wq = (const float*)d_in[1];
    const float* bq = (const float*)d_in[2];
    const float* Wk = (const float*)d_in[3];
    const float* bk = (const float*)d_in[4];
    const float* Wv = (const float*)d_in[5];
    const float* bv = (const float*)d_in[6];
    const float* Ww = (const float*)d_in[7];
    const float* bw = (const float*)d_in[8];
    float* out = (float*)d_out;

    cudaFuncSetAttribute(proj_kernel,
        cudaFuncAttributeMaxDynamicSharedMemorySize, DSM);
    cudaFuncSetAttribute(attn_kernel,
        cudaFuncAttributeMaxDynamicSharedMemorySize, DSM);

    conv_kernel<<<5120, 256>>>(x, Wq, Wk);
    prep_u_kernel<<<5, 256>>>(Wv, bv, Ww);
    s_kernel<<<MTOT / 8, 256>>>(x);

    proj_kernel<<<PERSIST_CTAS, 256, DSM>>>(bq, bk);
    attn_kernel<<<PERSIST_CTAS, 256, DSM>>>();

    combine_kernel<<<MTOT / 256, 256>>>(bw, out);
}

// round 14
// speedup vs baseline: 1.1673x; 1.0959x over previous
#include <cuda_runtime.h>
#include <cuda_fp16.h>
#include <cstdint>

#define D      1024
#define NTOK   2048
#define NB     4
#define MTOT   8192
#define NSPLIT 8

#define BK 64                       // k-chunk in elements (128 B of fp16)
#define NCH (D / BK)                // 16
#define BLK_BYTES 16384             // one 128x64 fp16 swizzled block
#define A_BYTES   BLK_BYTES
#define STAGE_BYTES (2 * BLK_BYTES) // A + B block
#define NSTAGE 3
#define DSM (NSTAGE * STAGE_BYTES + 1024)
#define SWZ(x) ((x) ^ (((x) >> 3) & 0x70))
#define CLOGF 0.045084220027780106f // log2(e)/sqrt(D)

#define NPROJ_TILES 512             // y = x@Mt^T : 64 rt x 8 ct
#define NATTN_TILES 512             // 4 b x 8 split x 16 ntq
#define PERSIST_CTAS 296

// Block layout for a [R x 1024] fp16 matrix (R multiple of 128):
//   byte(row, col) = ((row>>7)*16 + (col>>6))*16384 + SWZ((row&127)*128 + (col&63)*2)

// ---- scratch (device globals: allocation-free rule) ----
__device__ __half g_xb[MTOT * D];     // x, fp16 blocked
__device__ __half g_wqT[D * D];       // Wq^T blocked: (i,o) = Wq[o,i]
__device__ __half g_wkT[D * D];       // Wk^T blocked
__device__ __half g_mt[D * D];        // Mt = Wk^T@Wq (rows j, cols i) blocked
__device__ __half g_y[MTOT * D];      // y = x@Mt^T blocked
__device__ float  g_u[D];
__device__ float  g_cvec[D];          // bq @ Wk
__device__ float  g_c;
__device__ float2 g_sc[MTOT];         // (s_m, c_m*CLOG - 4)
__device__ float2 g_part[MTOT * NSPLIT];
__device__ unsigned int g_ctr[2];

// ============================ PTX helpers ============================
__device__ __forceinline__ uint32_t smem_u32(const void* p) {
    uint32_t a;
    asm("{ .reg .u64 t; cvta.to.shared.u64 t, %1; cvt.u32.u64 %0, t; }"
        : "=r"(a) : "l"(p));
    return a;
}
__device__ __forceinline__ uint32_t h2_bits(__half2 h) {
    union { __half2 h; uint32_t u; } cv;
    cv.h = h;
    return cv.u;
}
__device__ __forceinline__ void mbar_init(uint32_t bar, uint32_t cnt) {
    asm volatile("mbarrier.init.shared.b64 [%0], %1;" :: "r"(bar), "r"(cnt) : "memory");
}
__device__ __forceinline__ void expect_tx(uint32_t bar, uint32_t bytes) {
    asm volatile("mbarrier.arrive.expect_tx.shared.b64 _, [%0], %1;"
                 :: "r"(bar), "r"(bytes) : "memory");
}
__device__ __forceinline__ void bulk_g2s(uint32_t dst, const void* src,
                                         uint32_t bytes, uint32_t bar) {
    asm volatile(
        "cp.async.bulk.shared::cluster.global.mbarrier::complete_tx::bytes "
        "[%0], [%1], %2, [%3];"
        :: "r"(dst), "l"(src), "r"(bytes), "r"(bar) : "memory");
}
__device__ __forceinline__ void bar_wait(uint32_t bar, uint32_t parity) {
    asm volatile(
        "{\n\t.reg .pred P;\n"
        "W%=:\n\t"
        "mbarrier.try_wait.parity.shared.b64 P, [%0], %1;\n\t"
        "@!P bra W%=;\n\t}"
        :: "r"(bar), "r"(parity) : "memory");
}
#define FENCE_ASYNC() asm volatile("fence.proxy.async.shared::cta;" ::: "memory")

__device__ __forceinline__ void ldsm4(uint32_t* d, uint32_t addr) {
    asm volatile("ldmatrix.sync.aligned.m8n8.x4.shared.b16 {%0,%1,%2,%3}, [%4];"
                 : "=r"(d[0]), "=r"(d[1]), "=r"(d[2]), "=r"(d[3]) : "r"(addr));
}
__device__ __forceinline__ void mma16816(float* c, const uint32_t* a,
                                         uint32_t b0, uint32_t b1) {
    asm volatile(
        "mma.sync.aligned.m16n8k16.row.col.f32.f16.f16.f32 "
        "{%0,%1,%2,%3}, {%4,%5,%6,%7}, {%8,%9}, {%0,%1,%2,%3};"
        : "+f"(c[0]), "+f"(c[1]), "+f"(c[2]), "+f"(c[3])
        : "r"(a[0]), "r"(a[1]), "r"(a[2]), "r"(a[3]), "r"(b0), "r"(b1));
}

// fast 2^t on the FMA pipe
__device__ __forceinline__ float fexp2(float t) {
    t = fmaxf(t, -60.0f);
    float z = t + 12582912.0f;
    int   ki = __float_as_int(z);
    float n  = z - 12582912.0f;
    float f  = t - n;
    float p = 0.0013333558f;
    p = fmaf(p, f, 0.0096181291f);
    p = fmaf(p, f, 0.0555041087f);
    p = fmaf(p, f, 0.2402265070f);
    p = fmaf(p, f, 0.6931471806f);
    p = fmaf(p, f, 1.0f);
    return __int_as_float(__float_as_int(p) + (ki << 23));
}

// ============================ GEMM microkernel ============================
// C[128x128] += A_tile * B_tile^T over K=1024, pre-swizzled block layout.
// 3-stage bulk-copy pipeline; cnt[] carries mbar phases across calls.
__device__ __forceinline__ void gemm_tile(uint32_t sbase, uint32_t mbar,
                                          const char* srcA, const char* srcB,
                                          int tid, int cnt[NSTAGE],
                                          float c[4][4][4]) {
    const int lane = tid & 31, warp = tid >> 5;
    const int mw = warp & 1, nw = warp >> 1;
    const int q2 = lane >> 3, r = lane & 7;
    const int kbh = (q2 >> 1) * 16;
    uint32_t aoff[4], boff[2];
    #pragma unroll
    for (int mt = 0; mt < 4; mt++)
        aoff[mt] = (uint32_t)((mw * 64 + mt * 16 + (q2 & 1) * 8 + r) * 128 + kbh);
    #pragma unroll
    for (int nb = 0; nb < 2; nb++)
        boff[nb] = (uint32_t)((nw * 32 + nb * 16 + (q2 & 1) * 8 + r) * 128 + kbh);

    if (tid == 0) {
        #pragma unroll
        for (int s = 0; s < NSTAGE; s++) {
            expect_tx(mbar + s * 8, 2 * BLK_BYTES);
            bulk_g2s(sbase + s * STAGE_BYTES,           srcA + s * BLK_BYTES,
                     BLK_BYTES, mbar + s * 8);
            bulk_g2s(sbase + s * STAGE_BYTES + A_BYTES, srcB + s * BLK_BYTES,
                     BLK_BYTES, mbar + s * 8);
        }
    }

    #pragma unroll 1
    for (int g = 0; g < NCH; g++) {
        int s = g % NSTAGE;
        bar_wait(mbar + s * 8, cnt[s] & 1);
        cnt[s]++;

        uint32_t sA = sbase + s * STAGE_BYTES;
        uint32_t sB = sA + A_BYTES;
        #pragma unroll
        for (int ks = 0; ks < 4; ks++) {
            int kd = ks * 32;
            uint32_t a[4][4], b[2][4];
            #pragma unroll
            for (int mt = 0; mt < 4; mt++) ldsm4(a[mt], sA + SWZ(aoff[mt] + kd));
            #pragma unroll
            for (int nb = 0; nb < 2; nb++) ldsm4(b[nb], sB + SWZ(boff[nb] + kd));
            #pragma unroll
            for (int mt = 0; mt < 4; mt++)
                #pragma unroll
                for (int nt = 0; nt < 4; nt++)
                    mma16816(c[mt][nt], a[mt],
                             b[nt >> 1][nt & 1], b[nt >> 1][(nt & 1) + 2]);
        }
        __syncthreads();
        if (tid == 0 && g + NSTAGE < NCH) {
            expect_tx(mbar + s * 8, 2 * BLK_BYTES);
            bulk_g2s(sA,           srcA + (size_t)(g + NSTAGE) * BLK_BYTES,
                     BLK_BYTES, mbar + s * 8);
            bulk_g2s(sA + A_BYTES, srcB + (size_t)(g + NSTAGE) * BLK_BYTES,
                     BLK_BYTES, mbar + s * 8);
        }
    }
}

__device__ __forceinline__ void mbar_setup(uint32_t mbar, int tid) {
    if (tid == 0) {
        #pragma unroll
        for (int s = 0; s < NSTAGE; s++) mbar_init(mbar + s * 8, 1);
        FENCE_ASYNC();
    }
    __syncthreads();
}

// fp16-blocked epilogue write (no bias): C fragment -> blocked dst
__device__ __forceinline__ void epi_write(char* out, int rowtile, int coltile,
                                          int tid, float c[4][4][4],
                                          float b0v, float b1v, bool use_bias,
                                          const float* s_bias) {
    const int lane = tid & 31, warp = tid >> 5;
    const int mw = warp & 1, nw = warp >> 1;
    const int gq = lane >> 2, tg = lane & 3;
    #pragma unroll
    for (int mt = 0; mt < 4; mt++) {
        int rowL = mw * 64 + mt * 16 + gq;
        #pragma unroll
        for (int nt = 0; nt < 4; nt++) {
            int colL = nw * 32 + nt * 8 + 2 * tg;
            int col  = coltile * 128 + colL;
            float b0 = use_bias ? s_bias[colL] : 0.f;
            float b1 = use_bias ? s_bias[colL + 1] : 0.f;
            float* cc = c[mt][nt];
            size_t blk = ((size_t)(rowtile * 16 + (col >> 6))) * BLK_BYTES;
            uint32_t cb = (uint32_t)((col & 63) * 2);
            *(__half2*)(out + blk + SWZ((uint32_t)( rowL      * 128) + cb)) =
                __floats2half2_rn(cc[0] + b0, cc[1] + b1);
            *(__half2*)(out + blk + SWZ((uint32_t)((rowL + 8) * 128) + cb)) =
                __floats2half2_rn(cc[2] + b0, cc[3] + b1);
        }
    }
}

// ============================ small kernels ============================
// fp32 -> fp16 swizzled-block conversion for x only
__global__ void conv_x_kernel(const float* __restrict__ x) {
    size_t gid = (size_t)blockIdx.x * 256 + threadIdx.x;
    size_t e = gid * 8;
    int row = (int)(e >> 10);
    int col = (int)(e & 1023);
    const float4* s4 = (const float4*)(x + e);
    float4 v0 = s4[0], v1 = s4[1];
    uint4 o;
    o.x = h2_bits(__floats2half2_rn(v0.x, v0.y));
    o.y = h2_bits(__floats2half2_rn(v0.z, v0.w));
    o.z = h2_bits(__floats2half2_rn(v1.x, v1.y));
    o.w = h2_bits(__floats2half2_rn(v1.z, v1.w));
    uint32_t inblk = SWZ((uint32_t)((row & 127) * 128 + (col & 63) * 2));
    size_t byte = ((size_t)((row >> 7) * 16 + (col >> 6))) * BLK_BYTES + inblk;
    *(uint4*)((char*)g_xb + byte) = o;
}

// transposed fp16 conversion: g_wT(i,o) = W[o,i], blocked layout
__global__ void conv_wT_kernel(const float* __restrict__ Wq,
                               const float* __restrict__ Wk) {
    int g = blockIdx.x * 256 + threadIdx.x;       // 0..262143
    const float* src = (g < 131072) ? Wq : Wk;
    char* dst        = (g < 131072) ? (char*)g_wqT : (char*)g_wkT;
    int gm = g & 131071;
    int i  = gm & 1023;                           // coalesced read index
    int ob = (gm >> 10) << 3;                     // o base 0..1016
    float v0 = src[(size_t)(ob + 0) * D + i];
    float v1 = src[(size_t)(ob + 1) * D + i];
    float v2 = src[(size_t)(ob + 2) * D + i];
    float v3 = src[(size_t)(ob + 3) * D + i];
    float v4 = src[(size_t)(ob + 4) * D + i];
    float v5 = src[(size_t)(ob + 5) * D + i];
    float v6 = src[(size_t)(ob + 6) * D + i];
    float v7 = src[(size_t)(ob + 7) * D + i];
    uint4 o;
    o.x = h2_bits(__floats2half2_rn(v0, v1));
    o.y = h2_bits(__floats2half2_rn(v2, v3));
    o.z = h2_bits(__floats2half2_rn(v4, v5));
    o.w = h2_bits(__floats2half2_rn(v6, v7));
    uint32_t inblk = SWZ((uint32_t)((i & 127) * 128 + (ob & 63) * 2));
    size_t byte = ((size_t)((i >> 7) * 16 + (ob >> 6))) * BLK_BYTES + inblk;
    *(uint4*)(dst + byte) = o;
}

__global__ void prep_u_kernel(const float* __restrict__ Wv,
                              const float* __restrict__ bv,
                              const float* __restrict__ Ww,
                              const float* __restrict__ Wk,
                              const float* __restrict__ bq) {
    if (blockIdx.x < 4) {                          // u = Ww @ Wv
        int e = blockIdx.x * 256 + threadIdx.x;
        float sum = 0.f;
        #pragma unroll 8
        for (int d = 0; d < D; d++) sum = fmaf(Ww[d], Wv[d * D + e], sum);
        g_u[e] = sum;
    } else if (blockIdx.x == 4) {                  // c = Ww·bv + counters
        __shared__ float red[256];
        float s = 0.f;
        for (int d = threadIdx.x; d < D; d += 256) s = fmaf(Ww[d], bv[d], s);
        red[threadIdx.x] = s;
        __syncthreads();
        for (int off = 128; off > 0; off >>= 1) {
            if (threadIdx.x < off) red[threadIdx.x] += red[threadIdx.x + off];
            __syncthreads();
        }
        if (threadIdx.x == 0) {
            g_c = red[0];
            g_ctr[0] = 0;
            g_ctr[1] = 0;
        }
    } else {                                       // cvec = bq @ Wk
        int e = (blockIdx.x - 5) * 256 + threadIdx.x;
        float sum = 0.f;
        #pragma unroll 8
        for (int d = 0; d < D; d++) sum = fmaf(bq[d], Wk[d * D + e], sum);
        g_cvec[e] = sum;
    }
}

// per row: s = x·u + c ; cb = (x·cvec)*CLOG - 4
__global__ void s_kernel(const float* __restrict__ x) {
    int row  = blockIdx.x * 8 + (threadIdx.x >> 5);
    int lane = threadIdx.x & 31;
    const float4* xr = (const float4*)(x + (size_t)row * D);
    const float4* u4 = (const float4*)g_u;
    const float4* c4 = (const float4*)g_cvec;
    float su = 0.f, sc = 0.f;
    #pragma unroll
    for (int i = 0; i < 8; i++) {
        float4 a = xr[lane + i * 32];
        float4 b = u4[lane + i * 32];
        float4 cv = c4[lane + i * 32];
        su += a.x * b.x + a.y * b.y + a.z * b.z + a.w * b.w;
        sc += a.x * cv.x + a.y * cv.y + a.z * cv.z + a.w * cv.w;
    }
    #pragma unroll
    for (int off = 16; off > 0; off >>= 1) {
        su += __shfl_xor_sync(0xffffffffu, su, off);
        sc += __shfl_xor_sync(0xffffffffu, sc, off);
    }
    if (lane == 0)
        g_sc[row] = make_float2(su + g_c, sc * CLOGF - 4.0f);
}

// ============================ Mt GEMM ============================
// Mt[j,i] = sum_o Wk[o,j] Wq[o,i] : A = g_wkT (rows j), B = g_wqT (rows i)
__global__ __launch_bounds__(256, 2)
void mgemm_kernel() {
    extern __shared__ char dsm[];
    __shared__ __align__(8) uint64_t s_bar[NSTAGE];
    const int tid = threadIdx.x;
    uint32_t sbase = (smem_u32(dsm) + 1023u) & ~1023u;
    uint32_t mbar  = smem_u32(s_bar);
    mbar_setup(mbar, tid);

    const int jt = blockIdx.x, it = blockIdx.y;
    float cacc[4][4][4];
    #pragma unroll
    for (int a = 0; a < 4; a++)
        #pragma unroll
        for (int b = 0; b < 4; b++)
            #pragma unroll
            for (int e = 0; e < 4; e++) cacc[a][b][e] = 0.f;

    int cnt[NSTAGE] = {0, 0, 0};
    gemm_tile(sbase, mbar,
              (const char*)g_wkT + (size_t)jt * 16 * BLK_BYTES,
              (const char*)g_wqT + (size_t)it * 16 * BLK_BYTES,
              tid, cnt, cacc);
    epi_write((char*)g_mt, jt, it, tid, cacc, 0.f, 0.f, false, nullptr);
}

// ============================ y projection ============================
// y = x @ Mt^T : persistent, 512 tiles (64 rt x 8 ct)
__global__ __launch_bounds__(256, 2)
void proj_kernel() {
    extern __shared__ char dsm[];
    __shared__ __align__(8) uint64_t s_bar[NSTAGE];
    __shared__ int s_tile;

    const int tid  = threadIdx.x;
    uint32_t sbase = (smem_u32(dsm) + 1023u) & ~1023u;
    uint32_t mbar  = smem_u32(s_bar);
    mbar_setup(mbar, tid);
    int cnt[NSTAGE] = {0, 0, 0};

    for (;;) {
        __syncthreads();
        if (tid == 0) s_tile = (int)atomicAdd(&g_ctr[0], 1u);
        __syncthreads();
        int t = s_tile;
        if (t >= NPROJ_TILES) break;
        int ct = t >> 6;                 // consecutive tickets share ct
        int rt = t & 63;

        float cacc[4][4][4];
        #pragma unroll
        for (int a = 0; a < 4; a++)
            #pragma unroll
            for (int b = 0; b < 4; b++)
                #pragma unroll
                for (int e = 0; e < 4; e++) cacc[a][b][e] = 0.f;

        gemm_tile(sbase, mbar,
                  (const char*)g_xb + (size_t)rt * 16 * BLK_BYTES,
                  (const char*)g_mt + (size_t)ct * 16 * BLK_BYTES,
                  tid, cnt, cacc);
        epi_write((char*)g_y, rt, ct, tid, cacc, 0.f, 0.f, false, nullptr);
    }
}

// ============================ attention kernel ============================
// logits = y · x^T ; per-key bias cb folded into exp2 argument.
__global__ __launch_bounds__(256, 2)
void attn_kernel() {
    extern __shared__ char dsm[];
    __shared__ __align__(8) uint64_t s_bar[NSTAGE];
    __shared__ float2 s_sm[128];
    __shared__ float s_red[128][4][2];
    __shared__ int s_tile;

    const int tid  = threadIdx.x;
    uint32_t sbase = (smem_u32(dsm) + 1023u) & ~1023u;
    uint32_t mbar  = smem_u32(s_bar);
    mbar_setup(mbar, tid);

    const int lane = tid & 31, warp = tid >> 5;
    const int mw = warp & 1, nw = warp >> 1;
    const int gq = lane >> 2, tg = lane & 3;
    int cnt[NSTAGE] = {0, 0, 0};

    for (;;) {
        __syncthreads();
        if (tid == 0) s_tile = (int)atomicAdd(&g_ctr[1], 1u);
        __syncthreads();
        int t = s_tile;
        if (t >= NATTN_TILES) break;
        int b     = t >> 7;
        int rm    = t & 127;
        int split = rm >> 4;
        int nt_q  = rm & 15;
        const int row0 = b * NTOK + nt_q * 128;

        float num[4][2], den[4][2];
        #pragma unroll
        for (int mt = 0; mt < 4; mt++)
            #pragma unroll
            for (int h = 0; h < 2; h++) { num[mt][h] = 0.f; den[mt][h] = 0.f; }

        #pragma unroll 1
        for (int blk = 0; blk < 2; blk++) {
            const int kb = b * NTOK + split * 256 + blk * 128;
            if (tid < 128) s_sm[tid] = g_sc[kb + tid];
            // (gemm_tile's internal __syncthreads orders this before epilogue)

            float cacc[4][4][4];
            #pragma unroll
            for (int a = 0; a < 4; a++)
                #pragma unroll
                for (int c = 0; c < 4; c++)
                    #pragma unroll
                    for (int e = 0; e < 4; e++) cacc[a][c][e] = 0.f;

            gemm_tile(sbase, mbar,
                      (const char*)g_y  + (size_t)(row0 >> 7) * 16 * BLK_BYTES,
                      (const char*)g_xb + (size_t)(kb   >> 7) * 16 * BLK_BYTES,
                      tid, cnt, cacc);

            #pragma unroll
            for (int mt = 0; mt < 4; mt++)
                #pragma unroll
                for (int nt = 0; nt < 4; nt++) {
                    int colL = nw * 32 + nt * 8 + 2 * tg;
                    float2 sv0 = s_sm[colL], sv1 = s_sm[colL + 1];
                    float* cc = cacc[mt][nt];
                    float e0 = fexp2(fmaf(cc[0], CLOGF, sv0.y));
                    float e1 = fexp2(fmaf(cc[1], CLOGF, sv1.y));
                    float e2 = fexp2(fmaf(cc[2], CLOGF, sv0.y));
                    float e3 = fexp2(fmaf(cc[3], CLOGF, sv1.y));
                    den[mt][0] += e0 + e1;
                    den[mt][1] += e2 + e3;
                    num[mt][0] = fmaf(e0, sv0.x, fmaf(e1, sv1.x, num[mt][0]));
                    num[mt][1] = fmaf(e2, sv0.x, fmaf(e3, sv1.x, num[mt][1]));
                }
            __syncthreads();
        }

        #pragma unroll
        for (int mt = 0; mt < 4; mt++)
            #pragma unroll
            for (int h = 0; h < 2; h++) {
                num[mt][h] += __shfl_xor_sync(0xffffffffu, num[mt][h], 1);
                num[mt][h] += __shfl_xor_sync(0xffffffffu, num[mt][h], 2);
                den[mt][h] += __shfl_xor_sync(0xffffffffu, den[mt][h], 1);
                den[mt][h] += __shfl_xor_sync(0xffffffffu, den[mt][h], 2);
            }
        if (tg == 0) {
            #pragma unroll
            for (int mt = 0; mt < 4; mt++)
                #pragma unroll
                for (int h = 0; h < 2; h++) {
                    int rowl = mw * 64 + mt * 16 + h * 8 + gq;
                    s_red[rowl][nw][0] = num[mt][h];
                    s_red[rowl][nw][1] = den[mt][h];
                }
        }
        __syncthreads();
        if (tid < 128) {
            float n = 0.f, d = 0.f;
            #pragma unroll
            for (int w = 0; w < 4; w++) { n += s_red[tid][w][0]; d += s_red[tid][w][1]; }
            g_part[(size_t)(row0 + tid) * NSPLIT + split] = make_float2(n, d);
        }
    }
}

// ============================ combine ============================
__global__ void combine_kernel(const float* __restrict__ bw,
                               float* __restrict__ out) {
    int row = blockIdx.x * 256 + threadIdx.x;
    float n = 0.f, d = 0.f;
    #pragma unroll
    for (int s = 0; s < NSPLIT; s++) {
        float2 p = g_part[(size_t)row * NSPLIT + s];
        n += p.x; d += p.y;
    }
    out[row] = n / d + bw[0];
}

// ============================ launcher ============================
extern "C" void kernel_launch(void* const* d_in, const int* in_sizes, int n_in,
                              void* d_out, int out_size) {
    const float* x  = (const float*)d_in[0];
    const float* Wq = (const float*)d_in[1];
    const float* bq = (const float*)d_in[2];
    const float* Wk = (const float*)d_in[3];
    const float* bk = (const float*)d_in[4];
    const float* Wv = (const float*)d_in[5];
    const float* bv = (const float*)d_in[6];
    const float* Ww = (const float*)d_in[7];
    const float* bw = (const float*)d_in[8];
    float* out = (float*)d_out;
    (void)bk;

    cudaFuncSetAttribute(mgemm_kernel,
        cudaFuncAttributeMaxDynamicSharedMemorySize, DSM);
    cudaFuncSetAttribute(proj_kernel,
        cudaFuncAttributeMaxDynamicSharedMemorySize, DSM);
    cudaFuncSetAttribute(attn_kernel,
        cudaFuncAttributeMaxDynamicSharedMemorySize, DSM);

    conv_x_kernel<<<4096, 256>>>(x);
    conv_wT_kernel<<<1024, 256>>>(Wq, Wk);
    prep_u_kernel<<<9, 256>>>(Wv, bv, Ww, Wk, bq);

    dim3 gm(8, 8);
    mgemm_kernel<<<gm, 256, DSM>>>();

    s_kernel<<<MTOT / 8, 256>>>(x);

    proj_kernel<<<PERSIST_CTAS, 256, DSM>>>();
    attn_kernel<<<PERSIST_CTAS, 256, DSM>>>();

    combine_kernel<<<MTOT / 256, 256>>>(bw, out);
}